// round 7
// baseline (speedup 1.0000x reference)
#include <cuda_runtime.h>
#include <cuda_bf16.h>
#include <cuda_fp16.h>
#include <cstdint>

#define SEQ 2048
#define HD  128
#define BM  128
#define BN  64
#define NTH 256
#define ITERS (SEQ / BN)

// Per buffer: KHI(16KB) KLO(16KB) VH(16KB) = 48KB; double buffered = 96KB.
#define TILE_B 16384
#define BUF_B  (3 * TILE_B)
#define SMEM_BYTES (2 * BUF_B)

// swizzled byte offset of element (row, d) inside a 64x128-bf16/fp16 tile
__device__ __forceinline__ uint32_t swz(int row, int d) {
    return ((uint32_t)row << 8) + ((((uint32_t)(d >> 3)) ^ (row & 7)) << 4) + (d & 7) * 2;
}

__device__ __forceinline__ uint32_t prmt_hi(float a, float b) {
    uint32_t r;
    asm("prmt.b32 %0, %1, %2, 0x7632;" : "=r"(r)
        : "r"(__float_as_uint(a)), "r"(__float_as_uint(b)));
    return r;
}
__device__ __forceinline__ uint32_t pack_lo(float a, float b) {
    float la = a - __uint_as_float(__float_as_uint(a) & 0xffff0000u);
    float lb = b - __uint_as_float(__float_as_uint(b) & 0xffff0000u);
    uint32_t r;
    asm("cvt.rn.bf16x2.f32 %0, %1, %2;" : "=r"(r) : "f"(lb), "f"(la));  // low = la
    return r;
}
__device__ __forceinline__ uint32_t pack_h2(float a, float b) {
    __half2 h = __floats2half2_rn(a, b);   // low = a
    return *(uint32_t*)&h;
}

__device__ __forceinline__ void mma16816(float* c, const uint32_t* a, uint32_t b0, uint32_t b1) {
    asm volatile(
        "mma.sync.aligned.m16n8k16.row.col.f32.bf16.bf16.f32 "
        "{%0,%1,%2,%3}, {%4,%5,%6,%7}, {%8,%9}, {%0,%1,%2,%3};"
        : "+f"(c[0]), "+f"(c[1]), "+f"(c[2]), "+f"(c[3])
        : "r"(a[0]), "r"(a[1]), "r"(a[2]), "r"(a[3]), "r"(b0), "r"(b1));
}
__device__ __forceinline__ void mma16816h(float* c, const uint32_t* a, uint32_t b0, uint32_t b1) {
    asm volatile(
        "mma.sync.aligned.m16n8k16.row.col.f32.f16.f16.f32 "
        "{%0,%1,%2,%3}, {%4,%5,%6,%7}, {%8,%9}, {%0,%1,%2,%3};"
        : "+f"(c[0]), "+f"(c[1]), "+f"(c[2]), "+f"(c[3])
        : "r"(a[0]), "r"(a[1]), "r"(a[2]), "r"(a[3]), "r"(b0), "r"(b1));
}
__device__ __forceinline__ void ldmx4(uint32_t* r, uint32_t addr) {
    asm volatile("ldmatrix.sync.aligned.m8n8.x4.shared.b16 {%0,%1,%2,%3}, [%4];"
                 : "=r"(r[0]), "=r"(r[1]), "=r"(r[2]), "=r"(r[3]) : "r"(addr));
}
__device__ __forceinline__ void ldmx4t(uint32_t* r, uint32_t addr) {
    asm volatile("ldmatrix.sync.aligned.m8n8.x4.trans.shared.b16 {%0,%1,%2,%3}, [%4];"
                 : "=r"(r[0]), "=r"(r[1]), "=r"(r[2]), "=r"(r[3]) : "r"(addr));
}
__device__ __forceinline__ void sts2(uint32_t addr, uint32_t x, uint32_t y) {
    asm volatile("st.shared.v2.b32 [%0], {%1, %2};" :: "r"(addr), "r"(x), "r"(y) : "memory");
}
__device__ __forceinline__ uint32_t smem_u32(const void* p) {
    uint32_t a;
    asm("{ .reg .u64 t; cvta.to.shared.u64 t, %1; cvt.u32.u64 %0, t; }" : "=r"(a) : "l"(p));
    return a;
}

// gmem fp32 [64][128] K-tile -> bf16 hi/lo swizzled smem
__device__ __forceinline__ void load_k(const float* __restrict__ gp,
                                       uint32_t hi_b, uint32_t lo_b, int tid) {
#pragma unroll
    for (int t = 0; t < 8; ++t) {
        int idx = tid + t * NTH;
        int r = idx >> 5;
        int d = (idx & 31) << 2;
        float4 x = *(const float4*)(gp + r * HD + d);
        uint32_t off = swz(r, d);
        sts2(hi_b + off, prmt_hi(x.x, x.y), prmt_hi(x.z, x.w));
        sts2(lo_b + off, pack_lo(x.x, x.y), pack_lo(x.z, x.w));
    }
}
// gmem fp32 [64][128] V-tile -> fp16 swizzled smem
__device__ __forceinline__ void load_v(const float* __restrict__ gp,
                                       uint32_t vb, int tid) {
#pragma unroll
    for (int t = 0; t < 8; ++t) {
        int idx = tid + t * NTH;
        int r = idx >> 5;
        int d = (idx & 31) << 2;
        float4 x = *(const float4*)(gp + r * HD + d);
        sts2(vb + swz(r, d), pack_h2(x.x, x.y), pack_h2(x.z, x.w));
    }
}

__global__ void __launch_bounds__(NTH, 1)
adaptive_attn_mma(const float* __restrict__ q,
                  const float* __restrict__ k,
                  const float* __restrict__ v,
                  const float* __restrict__ alpha_p,
                  float* __restrict__ out) {
    extern __shared__ char smem[];
    const uint32_t sb = smem_u32(smem);
    const int tid = threadIdx.x;
    const int w = tid >> 5;
    const int lane = tid & 31;
    const int qq = lane & 3;
    const int jj = lane & 7;
    const int g = lane >> 3;
    const int rowadd = jj + ((g >> 1) << 3);
    const int csel = g & 1;
    const int row0 = w * 16 + (lane >> 2);

    const int qt = blockIdx.x;
    const int bh = blockIdx.y;
    const float av = alpha_p[0];

    const float* qg = q + ((long)bh * SEQ + (long)qt * BM) * HD;
    const float* kg = k + (long)bh * SEQ * HD;
    const float* vg = v + (long)bh * SEQ * HD;

    // ---- Q fragments (bf16 hi/lo), register-resident ----
    uint32_t qah[8][4], qal[8][4];
#pragma unroll
    for (int kk = 0; kk < 8; ++kk)
#pragma unroll
        for (int r = 0; r < 4; ++r) {
            int qrow = row0 + (r & 1) * 8;
            int qcol = kk * 16 + qq * 2 + (r >> 1) * 8;
            float2 f = *(const float2*)(qg + qrow * HD + qcol);
            qah[kk][r] = prmt_hi(f.x, f.y);
            qal[kk][r] = pack_lo(f.x, f.y);
        }

    // ---- prologue ----
    load_k(kg, sb, sb + TILE_B, tid);
    load_v(vg, sb + 2 * TILE_B, tid);
    __syncthreads();

    float oacc[16][4];
#pragma unroll
    for (int i = 0; i < 16; ++i)
#pragma unroll
        for (int e = 0; e < 4; ++e) oacc[i][e] = 0.0f;
    float rs0 = 0.0f, rs1 = 0.0f;
    float m0 = -1e30f, m1 = -1e30f;

    for (int i = 0; i < ITERS; ++i) {
        const uint32_t bufb = sb + (uint32_t)(i & 1) * BUF_B;
        const uint32_t khi = bufb, klo = bufb + TILE_B;
        const uint32_t vh = bufb + 2 * TILE_B;

        // ---- S = Q K^T (bf16x3) ----
        float sf[8][4];
#pragma unroll
        for (int nt = 0; nt < 8; ++nt)
#pragma unroll
            for (int e = 0; e < 4; ++e) sf[nt][e] = 0.0f;

#pragma unroll
        for (int kk = 0; kk < 8; ++kk) {
#pragma unroll
            for (int np = 0; np < 4; ++np) {
                uint32_t off = ((uint32_t)(np * 16 + rowadd) << 8)
                             + ((((kk << 1) | csel) ^ jj) << 4);
                uint32_t bh4[4], bl4[4];
                ldmx4(bh4, khi + off);
                ldmx4(bl4, klo + off);
                mma16816(sf[2 * np],     qah[kk], bh4[0], bh4[1]);
                mma16816(sf[2 * np],     qah[kk], bl4[0], bl4[1]);
                mma16816(sf[2 * np],     qal[kk], bh4[0], bh4[1]);
                mma16816(sf[2 * np + 1], qah[kk], bh4[2], bh4[3]);
                mma16816(sf[2 * np + 1], qah[kk], bl4[2], bl4[3]);
                mma16816(sf[2 * np + 1], qal[kk], bh4[2], bh4[3]);
            }
        }

        // ---- online softmax: logits a = av*s; row max; rescale; p = exp(a-m) in fp16 ----
#pragma unroll
        for (int nt = 0; nt < 8; ++nt) {
            sf[nt][0] *= av; sf[nt][1] *= av; sf[nt][2] *= av; sf[nt][3] *= av;
        }
        float tm0 = -1e30f, tm1 = -1e30f;
#pragma unroll
        for (int nt = 0; nt < 8; ++nt) {
            tm0 = fmaxf(tm0, fmaxf(sf[nt][0], sf[nt][1]));
            tm1 = fmaxf(tm1, fmaxf(sf[nt][2], sf[nt][3]));
        }
        tm0 = fmaxf(tm0, __shfl_xor_sync(0xffffffffu, tm0, 1));
        tm0 = fmaxf(tm0, __shfl_xor_sync(0xffffffffu, tm0, 2));
        tm1 = fmaxf(tm1, __shfl_xor_sync(0xffffffffu, tm1, 1));
        tm1 = fmaxf(tm1, __shfl_xor_sync(0xffffffffu, tm1, 2));
        const float m0n = fmaxf(m0, tm0);
        const float m1n = fmaxf(m1, tm1);
        const float sc0 = __expf(m0 - m0n);
        const float sc1 = __expf(m1 - m1n);
        m0 = m0n; m1 = m1n;

        float ts0 = 0.0f, ts1 = 0.0f;
        uint32_t ph[4][4];
#pragma unroll
        for (int nt = 0; nt < 8; ++nt) {
            float p0 = __expf(sf[nt][0] - m0n);
            float p1 = __expf(sf[nt][1] - m0n);
            float p2 = __expf(sf[nt][2] - m1n);
            float p3 = __expf(sf[nt][3] - m1n);
            ts0 += p0 + p1;
            ts1 += p2 + p3;
            sf[nt][0] = p0; sf[nt][1] = p1; sf[nt][2] = p2; sf[nt][3] = p3;
        }
        rs0 = rs0 * sc0 + ts0;
        rs1 = rs1 * sc1 + ts1;
#pragma unroll
        for (int kk = 0; kk < 4; ++kk) {
            ph[kk][0] = pack_h2(sf[2 * kk][0], sf[2 * kk][1]);
            ph[kk][1] = pack_h2(sf[2 * kk][2], sf[2 * kk][3]);
            ph[kk][2] = pack_h2(sf[2 * kk + 1][0], sf[2 * kk + 1][1]);
            ph[kk][3] = pack_h2(sf[2 * kk + 1][2], sf[2 * kk + 1][3]);
        }
#pragma unroll
        for (int dt = 0; dt < 16; ++dt) {
            oacc[dt][0] *= sc0; oacc[dt][1] *= sc0;
            oacc[dt][2] *= sc1; oacc[dt][3] *= sc1;
        }

        // ---- O += P V (single fp16 mma) ----
#pragma unroll
        for (int kk = 0; kk < 4; ++kk) {
#pragma unroll
            for (int dp = 0; dp < 8; ++dp) {
                uint32_t off = ((uint32_t)(kk * 16 + rowadd) << 8)
                             + ((((dp << 1) | csel) ^ jj) << 4);
                uint32_t bv[4];
                ldmx4t(bv, vh + off);
                mma16816h(oacc[2 * dp],     ph[kk], bv[0], bv[2]);
                mma16816h(oacc[2 * dp + 1], ph[kk], bv[1], bv[3]);
            }
        }

        // ---- load next tile ----
        if (i < ITERS - 1) {
            const uint32_t nb = sb + (uint32_t)((i + 1) & 1) * BUF_B;
            const float* kt = kg + (long)(i + 1) * BN * HD;
            const float* vt = vg + (long)(i + 1) * BN * HD;
            load_k(kt, nb, nb + TILE_B, tid);
            load_v(vt, nb + 2 * TILE_B, tid);
        }
        __syncthreads();
    }

    // ---- normalize + store ----
    rs0 += __shfl_xor_sync(0xffffffffu, rs0, 1);
    rs0 += __shfl_xor_sync(0xffffffffu, rs0, 2);
    rs1 += __shfl_xor_sync(0xffffffffu, rs1, 1);
    rs1 += __shfl_xor_sync(0xffffffffu, rs1, 2);
    const float inv0 = 1.0f / rs0;
    const float inv1 = 1.0f / rs1;

    float* og0 = out + ((long)bh * SEQ + (long)qt * BM + row0) * HD;
    float* og1 = og0 + 8 * HD;
#pragma unroll
    for (int dt = 0; dt < 16; ++dt) {
        int c = dt * 8 + qq * 2;
        float2 a, b;
        a.x = oacc[dt][0] * inv0; a.y = oacc[dt][1] * inv0;
        b.x = oacc[dt][2] * inv1; b.y = oacc[dt][3] * inv1;
        *(float2*)(og0 + c) = a;
        *(float2*)(og1 + c) = b;
    }
}

extern "C" void kernel_launch(void* const* d_in, const int* in_sizes, int n_in,
                              void* d_out, int out_size) {
    const float* q = (const float*)d_in[0];
    const float* k = (const float*)d_in[1];
    const float* v = (const float*)d_in[2];
    const float* alpha = (const float*)d_in[3];
    float* out = (float*)d_out;

    int bh = in_sizes[0] / (SEQ * HD);  // B*H = 32

    cudaFuncSetAttribute(adaptive_attn_mma,
                         cudaFuncAttributeMaxDynamicSharedMemorySize, SMEM_BYTES);

    dim3 grid(SEQ / BM, bh);
    adaptive_attn_mma<<<grid, NTH, SMEM_BYTES>>>(q, k, v, alpha, out);
}

// round 8
// speedup vs baseline: 1.3589x; 1.3589x over previous
#include <cuda_runtime.h>
#include <cuda_bf16.h>
#include <cstdint>

#define SEQ 2048
#define HD  128
#define BM  128
#define BN  64
#define NTH 384          // 8 consumer warps + 4 producer warps
#define NCONS 256
#define ITERS (SEQ / BN)

// ring: 2 stages x (KHI,KLO,VHI,VLO) 16KB each = 64KB/stage
#define TILE_B  16384
#define STAGE_B (4 * TILE_B)
#define SM_QHI  (2 * STAGE_B)          // 131072
#define SM_QLO  (SM_QHI + 32768)       // 163840
#define SMEM_BYTES (SM_QLO + 32768)    // 196608

// swizzled byte offset of (row, d) in a tile with 256B rows (bf16, 128 cols)
__device__ __forceinline__ uint32_t swz(int row, int d) {
    return ((uint32_t)row << 8) + ((((uint32_t)(d >> 3)) ^ (row & 7)) << 4) + (d & 7) * 2;
}

__device__ __forceinline__ uint32_t prmt_hi(float a, float b) {
    uint32_t r;
    asm("prmt.b32 %0, %1, %2, 0x7632;" : "=r"(r)
        : "r"(__float_as_uint(a)), "r"(__float_as_uint(b)));
    return r;
}
__device__ __forceinline__ uint32_t pack_lo(float a, float b) {
    float la = a - __uint_as_float(__float_as_uint(a) & 0xffff0000u);
    float lb = b - __uint_as_float(__float_as_uint(b) & 0xffff0000u);
    uint32_t r;
    asm("cvt.rn.bf16x2.f32 %0, %1, %2;" : "=r"(r) : "f"(lb), "f"(la));  // low = la
    return r;
}

__device__ __forceinline__ void mma16816(float* c, const uint32_t* a, uint32_t b0, uint32_t b1) {
    asm volatile(
        "mma.sync.aligned.m16n8k16.row.col.f32.bf16.bf16.f32 "
        "{%0,%1,%2,%3}, {%4,%5,%6,%7}, {%8,%9}, {%0,%1,%2,%3};"
        : "+f"(c[0]), "+f"(c[1]), "+f"(c[2]), "+f"(c[3])
        : "r"(a[0]), "r"(a[1]), "r"(a[2]), "r"(a[3]), "r"(b0), "r"(b1));
}
__device__ __forceinline__ void ldmx4(uint32_t* r, uint32_t addr) {
    asm volatile("ldmatrix.sync.aligned.m8n8.x4.shared.b16 {%0,%1,%2,%3}, [%4];"
                 : "=r"(r[0]), "=r"(r[1]), "=r"(r[2]), "=r"(r[3]) : "r"(addr));
}
__device__ __forceinline__ void ldmx4t(uint32_t* r, uint32_t addr) {
    asm volatile("ldmatrix.sync.aligned.m8n8.x4.trans.shared.b16 {%0,%1,%2,%3}, [%4];"
                 : "=r"(r[0]), "=r"(r[1]), "=r"(r[2]), "=r"(r[3]) : "r"(addr));
}
__device__ __forceinline__ void sts2(uint32_t addr, uint32_t x, uint32_t y) {
    asm volatile("st.shared.v2.b32 [%0], {%1, %2};" :: "r"(addr), "r"(x), "r"(y) : "memory");
}
__device__ __forceinline__ uint32_t smem_u32(const void* p) {
    uint32_t a;
    asm("{ .reg .u64 t; cvta.to.shared.u64 t, %1; cvt.u32.u64 %0, t; }" : "=r"(a) : "l"(p));
    return a;
}
__device__ __forceinline__ void mbar_init(uint32_t m, uint32_t cnt) {
    asm volatile("mbarrier.init.shared.b64 [%0], %1;" :: "r"(m), "r"(cnt) : "memory");
}
__device__ __forceinline__ void mbar_arrive(uint32_t m) {
    asm volatile("mbarrier.arrive.shared.b64 _, [%0];" :: "r"(m) : "memory");
}
__device__ __forceinline__ void mbar_wait(uint32_t m, uint32_t parity) {
    uint32_t done;
    asm volatile("{\n\t.reg .pred p;\n\t"
                 "mbarrier.try_wait.parity.acquire.cta.shared::cta.b64 p, [%1], %2;\n\t"
                 "selp.b32 %0, 1, 0, p;\n\t}"
                 : "=r"(done) : "r"(m), "r"(parity) : "memory");
    while (!done) {
        asm volatile("{\n\t.reg .pred p;\n\t"
                     "mbarrier.try_wait.parity.acquire.cta.shared::cta.b64 p, [%1], %2, 0x989680;\n\t"
                     "selp.b32 %0, 1, 0, p;\n\t}"
                     : "=r"(done) : "r"(m), "r"(parity) : "memory");
    }
}

__global__ void __launch_bounds__(NTH, 1)
adaptive_attn_ws(const float* __restrict__ q,
                 const float* __restrict__ k,
                 const float* __restrict__ v,
                 const float* __restrict__ alpha_p,
                 float* __restrict__ out) {
    extern __shared__ char smem[];
    __shared__ alignas(8) unsigned long long mbars[4];  // full0, full1, empty0, empty1
    const uint32_t sb = smem_u32(smem);
    const uint32_t mb = smem_u32(mbars);

    const int tid = threadIdx.x;
    const int qt = blockIdx.x;
    const int bh = blockIdx.y;
    const float av = alpha_p[0];

    const float* qg = q + ((long)bh * SEQ + (long)qt * BM) * HD;
    const float* kg = k + (long)bh * SEQ * HD;
    const float* vg = v + (long)bh * SEQ * HD;

    if (tid == 0) {
        mbar_init(mb + 0, 128);  // full[0]  : 128 producer threads
        mbar_init(mb + 8, 128);  // full[1]
        mbar_init(mb + 16, 8);   // empty[0] : 8 consumer warps (lane 0)
        mbar_init(mb + 24, 8);   // empty[1]
    }

    // ---- prologue: Q (alpha folded) -> bf16 hi/lo swizzled smem, all threads ----
    for (int idx = tid; idx < BM * HD / 4; idx += NTH) {
        int r = idx >> 5;
        int d = (idx & 31) << 2;
        float4 x = *(const float4*)(qg + r * HD + d);
        x.x *= av; x.y *= av; x.z *= av; x.w *= av;
        uint32_t off = swz(r, d);
        sts2(sb + SM_QHI + off, prmt_hi(x.x, x.y), prmt_hi(x.z, x.w));
        sts2(sb + SM_QLO + off, pack_lo(x.x, x.y), pack_lo(x.z, x.w));
    }
    __syncthreads();

    if (tid >= NCONS) {
        // ================= PRODUCER (warps 8-11) =================
        const int pt = tid - NCONS;  // 0..127
        uint32_t pe = 1;             // empty-wait phase (first pass free)
        for (int i = 0; i < ITERS; ++i) {
            const int s = i & 1;
            mbar_wait(mb + 16 + 8 * s, pe);
            const uint32_t base = sb + (uint32_t)s * STAGE_B;
            const float* kp = kg + (long)i * BN * HD;
            const float* vp = vg + (long)i * BN * HD;
            float4 xb[8];
#pragma unroll
            for (int h = 0; h < 2; ++h) {
#pragma unroll
                for (int t = 0; t < 8; ++t) {
                    int idx = pt + (h * 8 + t) * 128;
                    xb[t] = *(const float4*)(kp + (idx >> 5) * HD + ((idx & 31) << 2));
                }
#pragma unroll
                for (int t = 0; t < 8; ++t) {
                    int idx = pt + (h * 8 + t) * 128;
                    uint32_t off = swz(idx >> 5, (idx & 31) << 2);
                    sts2(base + off, prmt_hi(xb[t].x, xb[t].y), prmt_hi(xb[t].z, xb[t].w));
                    sts2(base + TILE_B + off, pack_lo(xb[t].x, xb[t].y), pack_lo(xb[t].z, xb[t].w));
                }
            }
#pragma unroll
            for (int h = 0; h < 2; ++h) {
#pragma unroll
                for (int t = 0; t < 8; ++t) {
                    int idx = pt + (h * 8 + t) * 128;
                    xb[t] = *(const float4*)(vp + (idx >> 5) * HD + ((idx & 31) << 2));
                }
#pragma unroll
                for (int t = 0; t < 8; ++t) {
                    int idx = pt + (h * 8 + t) * 128;
                    uint32_t off = swz(idx >> 5, (idx & 31) << 2);
                    sts2(base + 2 * TILE_B + off, prmt_hi(xb[t].x, xb[t].y), prmt_hi(xb[t].z, xb[t].w));
                    sts2(base + 3 * TILE_B + off, pack_lo(xb[t].x, xb[t].y), pack_lo(xb[t].z, xb[t].w));
                }
            }
            mbar_arrive(mb + 8 * s);  // full[s]
            if (s == 1) pe ^= 1;
        }
        return;
    }

    // ================= CONSUMER (warps 0-7) =================
    const int w = tid >> 5;
    const int lane = tid & 31;
    const int qq = lane & 3;
    const int jj = lane & 7;
    const int g = lane >> 3;
    const int rowadd = jj + ((g >> 1) << 3);   // B-operand ldmatrix row offset
    const int csel = g & 1;                    // B-operand chunk offset
    const int arow = w * 16 + ((g & 1) << 3) + jj;  // A-operand ldmatrix row
    const int asel = g >> 1;                        // A-operand 8-col block
    const int row0 = w * 16 + (lane >> 2);

    float oacc[16][4];
#pragma unroll
    for (int i = 0; i < 16; ++i)
#pragma unroll
        for (int e = 0; e < 4; ++e) oacc[i][e] = 0.0f;
    float rs0 = 0.0f, rs1 = 0.0f;
    uint32_t pf = 0;  // full-wait phase

    const uint32_t qhi_b = sb + SM_QHI;
    const uint32_t qlo_b = sb + SM_QLO;

    for (int i = 0; i < ITERS; ++i) {
        const int s = i & 1;
        mbar_wait(mb + 8 * s, pf);
        const uint32_t base = sb + (uint32_t)s * STAGE_B;
        const uint32_t khi = base, klo = base + TILE_B;
        const uint32_t vhi = base + 2 * TILE_B, vlo = base + 3 * TILE_B;

        // ---- S = (alpha Q) K^T, bf16x3 ----
        float sf[8][4];
#pragma unroll
        for (int nt = 0; nt < 8; ++nt)
#pragma unroll
            for (int e = 0; e < 4; ++e) sf[nt][e] = 0.0f;

#pragma unroll
        for (int kk = 0; kk < 8; ++kk) {
            uint32_t qa_h[4], qa_l[4];
            uint32_t aoff = ((uint32_t)arow << 8) + ((((kk << 1) | asel) ^ jj) << 4);
            ldmx4(qa_h, qhi_b + aoff);
            ldmx4(qa_l, qlo_b + aoff);
#pragma unroll
            for (int np = 0; np < 4; ++np) {
                uint32_t off = ((uint32_t)(np * 16 + rowadd) << 8)
                             + ((((kk << 1) | csel) ^ jj) << 4);
                uint32_t bh4[4], bl4[4];
                ldmx4(bh4, khi + off);
                ldmx4(bl4, klo + off);
                mma16816(sf[2 * np],     qa_h, bh4[0], bh4[1]);
                mma16816(sf[2 * np],     qa_h, bl4[0], bl4[1]);
                mma16816(sf[2 * np],     qa_l, bh4[0], bh4[1]);
                mma16816(sf[2 * np + 1], qa_h, bh4[2], bh4[3]);
                mma16816(sf[2 * np + 1], qa_h, bl4[2], bl4[3]);
                mma16816(sf[2 * np + 1], qa_l, bh4[2], bh4[3]);
            }
        }

        // ---- P = exp(S) (no max needed: |logit| <= ~40); split bf16 hi/lo ----
        uint32_t ph[4][4], pl[4][4];
#pragma unroll
        for (int nt = 0; nt < 8; ++nt) {
            float p0 = __expf(sf[nt][0]);
            float p1 = __expf(sf[nt][1]);
            float p2 = __expf(sf[nt][2]);
            float p3 = __expf(sf[nt][3]);
            rs0 += p0 + p1;
            rs1 += p2 + p3;
            sf[nt][0] = p0; sf[nt][1] = p1; sf[nt][2] = p2; sf[nt][3] = p3;
        }
#pragma unroll
        for (int kk = 0; kk < 4; ++kk) {
            ph[kk][0] = prmt_hi(sf[2 * kk][0], sf[2 * kk][1]);
            ph[kk][1] = prmt_hi(sf[2 * kk][2], sf[2 * kk][3]);
            ph[kk][2] = prmt_hi(sf[2 * kk + 1][0], sf[2 * kk + 1][1]);
            ph[kk][3] = prmt_hi(sf[2 * kk + 1][2], sf[2 * kk + 1][3]);
            pl[kk][0] = pack_lo(sf[2 * kk][0], sf[2 * kk][1]);
            pl[kk][1] = pack_lo(sf[2 * kk][2], sf[2 * kk][3]);
            pl[kk][2] = pack_lo(sf[2 * kk + 1][0], sf[2 * kk + 1][1]);
            pl[kk][3] = pack_lo(sf[2 * kk + 1][2], sf[2 * kk + 1][3]);
        }

        // ---- O += P V (bf16x3), V via ldmatrix.trans ----
#pragma unroll
        for (int kk = 0; kk < 4; ++kk) {
#pragma unroll
            for (int dp = 0; dp < 8; ++dp) {
                uint32_t off = ((uint32_t)(kk * 16 + rowadd) << 8)
                             + ((((dp << 1) | csel) ^ jj) << 4);
                uint32_t bh4[4], bl4[4];
                ldmx4t(bh4, vhi + off);
                ldmx4t(bl4, vlo + off);
                mma16816(oacc[2 * dp],     ph[kk], bh4[0], bh4[2]);
                mma16816(oacc[2 * dp],     ph[kk], bl4[0], bl4[2]);
                mma16816(oacc[2 * dp],     pl[kk], bh4[0], bh4[2]);
                mma16816(oacc[2 * dp + 1], ph[kk], bh4[1], bh4[3]);
                mma16816(oacc[2 * dp + 1], ph[kk], bl4[1], bl4[3]);
                mma16816(oacc[2 * dp + 1], pl[kk], bh4[1], bh4[3]);
            }
        }

        if (lane == 0) mbar_arrive(mb + 16 + 8 * s);  // empty[s]
        if (s == 1) pf ^= 1;
    }

    // ---- normalize + store ----
    rs0 += __shfl_xor_sync(0xffffffffu, rs0, 1);
    rs0 += __shfl_xor_sync(0xffffffffu, rs0, 2);
    rs1 += __shfl_xor_sync(0xffffffffu, rs1, 1);
    rs1 += __shfl_xor_sync(0xffffffffu, rs1, 2);
    const float inv0 = 1.0f / rs0;
    const float inv1 = 1.0f / rs1;

    float* og0 = out + ((long)bh * SEQ + (long)qt * BM + row0) * HD;
    float* og1 = og0 + 8 * HD;
#pragma unroll
    for (int dt = 0; dt < 16; ++dt) {
        int c = dt * 8 + qq * 2;
        float2 a, b;
        a.x = oacc[dt][0] * inv0; a.y = oacc[dt][1] * inv0;
        b.x = oacc[dt][2] * inv1; b.y = oacc[dt][3] * inv1;
        *(float2*)(og0 + c) = a;
        *(float2*)(og1 + c) = b;
    }
}

extern "C" void kernel_launch(void* const* d_in, const int* in_sizes, int n_in,
                              void* d_out, int out_size) {
    const float* q = (const float*)d_in[0];
    const float* k = (const float*)d_in[1];
    const float* v = (const float*)d_in[2];
    const float* alpha = (const float*)d_in[3];
    float* out = (float*)d_out;

    int bh = in_sizes[0] / (SEQ * HD);  // B*H = 32

    cudaFuncSetAttribute(adaptive_attn_ws,
                         cudaFuncAttributeMaxDynamicSharedMemorySize, SMEM_BYTES);

    dim3 grid(SEQ / BM, bh);
    adaptive_attn_ws<<<grid, NTH, SMEM_BYTES>>>(q, k, v, alpha, out);
}

// round 9
// speedup vs baseline: 1.3725x; 1.0100x over previous
#include <cuda_runtime.h>
#include <cuda_bf16.h>
#include <cstdint>

#define SEQ 2048
#define HD  128
#define BM  128
#define BN  64
#define NTH 384          // 8 consumer warps + 4 producer warps
#define NCONS 256
#define ITERS (SEQ / BN)

// ring: 2 stages x (KHI,KLO,VHI,VLO) 16KB each = 64KB/stage
#define TILE_B  16384
#define STAGE_B (4 * TILE_B)
#define SM_QHI  (2 * STAGE_B)          // 131072
#define SM_QLO  (SM_QHI + 32768)       // 163840
#define SMEM_BYTES (SM_QLO + 32768)    // 196608

// swizzled byte offset of (row, d) in a tile with 256B rows (bf16, 128 cols)
__device__ __forceinline__ uint32_t swz(int row, int d) {
    return ((uint32_t)row << 8) + ((((uint32_t)(d >> 3)) ^ (row & 7)) << 4) + (d & 7) * 2;
}

__device__ __forceinline__ uint32_t prmt_hi(float a, float b) {
    uint32_t r;
    asm("prmt.b32 %0, %1, %2, 0x7632;" : "=r"(r)
        : "r"(__float_as_uint(a)), "r"(__float_as_uint(b)));
    return r;
}
__device__ __forceinline__ uint32_t pack_lo(float a, float b) {
    float la = a - __uint_as_float(__float_as_uint(a) & 0xffff0000u);
    float lb = b - __uint_as_float(__float_as_uint(b) & 0xffff0000u);
    uint32_t r;
    asm("cvt.rn.bf16x2.f32 %0, %1, %2;" : "=r"(r) : "f"(lb), "f"(la));  // low = la
    return r;
}

__device__ __forceinline__ void mma16816(float* c, const uint32_t* a, uint32_t b0, uint32_t b1) {
    asm volatile(
        "mma.sync.aligned.m16n8k16.row.col.f32.bf16.bf16.f32 "
        "{%0,%1,%2,%3}, {%4,%5,%6,%7}, {%8,%9}, {%0,%1,%2,%3};"
        : "+f"(c[0]), "+f"(c[1]), "+f"(c[2]), "+f"(c[3])
        : "r"(a[0]), "r"(a[1]), "r"(a[2]), "r"(a[3]), "r"(b0), "r"(b1));
}
__device__ __forceinline__ void ldmx4(uint32_t* r, uint32_t addr) {
    asm volatile("ldmatrix.sync.aligned.m8n8.x4.shared.b16 {%0,%1,%2,%3}, [%4];"
                 : "=r"(r[0]), "=r"(r[1]), "=r"(r[2]), "=r"(r[3]) : "r"(addr));
}
__device__ __forceinline__ void ldmx4t(uint32_t* r, uint32_t addr) {
    asm volatile("ldmatrix.sync.aligned.m8n8.x4.trans.shared.b16 {%0,%1,%2,%3}, [%4];"
                 : "=r"(r[0]), "=r"(r[1]), "=r"(r[2]), "=r"(r[3]) : "r"(addr));
}
__device__ __forceinline__ void sts2(uint32_t addr, uint32_t x, uint32_t y) {
    asm volatile("st.shared.v2.b32 [%0], {%1, %2};" :: "r"(addr), "r"(x), "r"(y) : "memory");
}
__device__ __forceinline__ uint32_t smem_u32(const void* p) {
    uint32_t a;
    asm("{ .reg .u64 t; cvta.to.shared.u64 t, %1; cvt.u32.u64 %0, t; }" : "=r"(a) : "l"(p));
    return a;
}
__device__ __forceinline__ void mbar_init(uint32_t m, uint32_t cnt) {
    asm volatile("mbarrier.init.shared.b64 [%0], %1;" :: "r"(m), "r"(cnt) : "memory");
}
__device__ __forceinline__ void mbar_arrive(uint32_t m) {
    asm volatile("mbarrier.arrive.shared.b64 _, [%0];" :: "r"(m) : "memory");
}
__device__ __forceinline__ void mbar_wait(uint32_t m, uint32_t parity) {
    uint32_t done;
    asm volatile("{\n\t.reg .pred p;\n\t"
                 "mbarrier.try_wait.parity.acquire.cta.shared::cta.b64 p, [%1], %2;\n\t"
                 "selp.b32 %0, 1, 0, p;\n\t}"
                 : "=r"(done) : "r"(m), "r"(parity) : "memory");
    while (!done) {
        asm volatile("{\n\t.reg .pred p;\n\t"
                     "mbarrier.try_wait.parity.acquire.cta.shared::cta.b64 p, [%1], %2, 0x989680;\n\t"
                     "selp.b32 %0, 1, 0, p;\n\t}"
                     : "=r"(done) : "r"(m), "r"(parity) : "memory");
    }
}

__global__ void __launch_bounds__(NTH, 1)
adaptive_attn_ws(const float* __restrict__ q,
                 const float* __restrict__ k,
                 const float* __restrict__ v,
                 const float* __restrict__ alpha_p,
                 float* __restrict__ out) {
    extern __shared__ char smem[];
    __shared__ alignas(8) unsigned long long mbars[4];  // full0, full1, empty0, empty1
    const uint32_t sb = smem_u32(smem);
    const uint32_t mb = smem_u32(mbars);

    const int tid = threadIdx.x;
    const int qt = blockIdx.x;
    const int bh = blockIdx.y;
    const float av = alpha_p[0];

    const float* qg = q + ((long)bh * SEQ + (long)qt * BM) * HD;
    const float* kg = k + (long)bh * SEQ * HD;
    const float* vg = v + (long)bh * SEQ * HD;

    if (tid == 0) {
        mbar_init(mb + 0, 128);  // full[0]  : 128 producer threads
        mbar_init(mb + 8, 128);  // full[1]
        mbar_init(mb + 16, 8);   // empty[0] : 8 consumer warps (lane 0)
        mbar_init(mb + 24, 8);   // empty[1]
    }

    // ---- prologue: Q (alpha folded) -> bf16 hi/lo swizzled smem, all threads ----
    for (int idx = tid; idx < BM * HD / 4; idx += NTH) {
        int r = idx >> 5;
        int d = (idx & 31) << 2;
        float4 x = *(const float4*)(qg + r * HD + d);
        x.x *= av; x.y *= av; x.z *= av; x.w *= av;
        uint32_t off = swz(r, d);
        sts2(sb + SM_QHI + off, prmt_hi(x.x, x.y), prmt_hi(x.z, x.w));
        sts2(sb + SM_QLO + off, pack_lo(x.x, x.y), pack_lo(x.z, x.w));
    }
    __syncthreads();

    if (tid >= NCONS) {
        // ================= PRODUCER (warps 8-11) =================
        const int pt = tid - NCONS;  // 0..127
        uint32_t pe = 1;             // empty-wait phase (first pass free)
        for (int i = 0; i < ITERS; ++i) {
            const int s = i & 1;
            mbar_wait(mb + 16 + 8 * s, pe);
            const uint32_t base = sb + (uint32_t)s * STAGE_B;
            const float* kp = kg + (long)i * BN * HD;
            const float* vp = vg + (long)i * BN * HD;
            float4 xb[8];
#pragma unroll
            for (int h = 0; h < 2; ++h) {
#pragma unroll
                for (int t = 0; t < 8; ++t) {
                    int idx = pt + (h * 8 + t) * 128;
                    xb[t] = *(const float4*)(kp + (idx >> 5) * HD + ((idx & 31) << 2));
                }
#pragma unroll
                for (int t = 0; t < 8; ++t) {
                    int idx = pt + (h * 8 + t) * 128;
                    uint32_t off = swz(idx >> 5, (idx & 31) << 2);
                    sts2(base + off, prmt_hi(xb[t].x, xb[t].y), prmt_hi(xb[t].z, xb[t].w));
                    sts2(base + TILE_B + off, pack_lo(xb[t].x, xb[t].y), pack_lo(xb[t].z, xb[t].w));
                }
            }
#pragma unroll
            for (int h = 0; h < 2; ++h) {
#pragma unroll
                for (int t = 0; t < 8; ++t) {
                    int idx = pt + (h * 8 + t) * 128;
                    xb[t] = *(const float4*)(vp + (idx >> 5) * HD + ((idx & 31) << 2));
                }
#pragma unroll
                for (int t = 0; t < 8; ++t) {
                    int idx = pt + (h * 8 + t) * 128;
                    uint32_t off = swz(idx >> 5, (idx & 31) << 2);
                    sts2(base + 2 * TILE_B + off, prmt_hi(xb[t].x, xb[t].y), prmt_hi(xb[t].z, xb[t].w));
                    sts2(base + 3 * TILE_B + off, pack_lo(xb[t].x, xb[t].y), pack_lo(xb[t].z, xb[t].w));
                }
            }
            mbar_arrive(mb + 8 * s);  // full[s]
            if (s == 1) pe ^= 1;
        }
        return;
    }

    // ================= CONSUMER (warps 0-7) =================
    const int w = tid >> 5;
    const int lane = tid & 31;
    const int qq = lane & 3;
    const int jj = lane & 7;
    const int g = lane >> 3;
    const int rowadd = jj + ((g >> 1) << 3);        // B-operand ldmatrix row offset
    const int csel = g & 1;                         // B-operand chunk offset
    const int arow = w * 16 + ((g & 1) << 3) + jj;  // A-operand ldmatrix row
    const int asel = g >> 1;                        // A-operand 8-col block
    const int row0 = w * 16 + (lane >> 2);

    float oacc[16][4];
#pragma unroll
    for (int i = 0; i < 16; ++i)
#pragma unroll
        for (int e = 0; e < 4; ++e) oacc[i][e] = 0.0f;
    float rs0 = 0.0f, rs1 = 0.0f;
    uint32_t pf = 0;  // full-wait phase

    const uint32_t qhi_b = sb + SM_QHI;
    const uint32_t qlo_b = sb + SM_QLO;

    for (int i = 0; i < ITERS; ++i) {
        const int s = i & 1;
        mbar_wait(mb + 8 * s, pf);
        const uint32_t base = sb + (uint32_t)s * STAGE_B;
        const uint32_t khi = base, klo = base + TILE_B;
        const uint32_t vhi = base + 2 * TILE_B, vlo = base + 3 * TILE_B;

        // ---- S = (alpha Q) K^T, bf16x3 ----
        float sf[8][4];
#pragma unroll
        for (int nt = 0; nt < 8; ++nt)
#pragma unroll
            for (int e = 0; e < 4; ++e) sf[nt][e] = 0.0f;

#pragma unroll
        for (int kk = 0; kk < 8; ++kk) {
            uint32_t qa_h[4], qa_l[4];
            uint32_t aoff = ((uint32_t)arow << 8) + ((((kk << 1) | asel) ^ jj) << 4);
            ldmx4(qa_h, qhi_b + aoff);
            ldmx4(qa_l, qlo_b + aoff);
#pragma unroll
            for (int np = 0; np < 4; ++np) {
                uint32_t off = ((uint32_t)(np * 16 + rowadd) << 8)
                             + ((((kk << 1) | csel) ^ jj) << 4);
                uint32_t bh4[4], bl4[4];
                ldmx4(bh4, khi + off);
                ldmx4(bl4, klo + off);
                mma16816(sf[2 * np],     qa_h, bh4[0], bh4[1]);
                mma16816(sf[2 * np],     qa_h, bl4[0], bl4[1]);
                mma16816(sf[2 * np],     qa_l, bh4[0], bh4[1]);
                mma16816(sf[2 * np + 1], qa_h, bh4[2], bh4[3]);
                mma16816(sf[2 * np + 1], qa_h, bl4[2], bl4[3]);
                mma16816(sf[2 * np + 1], qa_l, bh4[2], bh4[3]);
            }
        }

        // ---- interleaved: per 16-col chunk kk, exp+pack THEN its PV mmas ----
        // keeps MUFU/FMA of chunk kk+1 issuing while chunk kk's HMMAs drain.
#pragma unroll
        for (int kk = 0; kk < 4; ++kk) {
            float p00 = __expf(sf[2 * kk][0]);
            float p01 = __expf(sf[2 * kk][1]);
            float p02 = __expf(sf[2 * kk][2]);
            float p03 = __expf(sf[2 * kk][3]);
            float p10 = __expf(sf[2 * kk + 1][0]);
            float p11 = __expf(sf[2 * kk + 1][1]);
            float p12 = __expf(sf[2 * kk + 1][2]);
            float p13 = __expf(sf[2 * kk + 1][3]);
            rs0 += p00 + p01 + p10 + p11;
            rs1 += p02 + p03 + p12 + p13;

            uint32_t ph[4], pl[4];
            ph[0] = prmt_hi(p00, p01);
            ph[1] = prmt_hi(p02, p03);
            ph[2] = prmt_hi(p10, p11);
            ph[3] = prmt_hi(p12, p13);
            pl[0] = pack_lo(p00, p01);
            pl[1] = pack_lo(p02, p03);
            pl[2] = pack_lo(p10, p11);
            pl[3] = pack_lo(p12, p13);

#pragma unroll
            for (int dp = 0; dp < 8; ++dp) {
                uint32_t off = ((uint32_t)(kk * 16 + rowadd) << 8)
                             + ((((dp << 1) | csel) ^ jj) << 4);
                uint32_t bh4[4], bl4[4];
                ldmx4t(bh4, vhi + off);
                ldmx4t(bl4, vlo + off);
                mma16816(oacc[2 * dp],     ph, bh4[0], bh4[2]);
                mma16816(oacc[2 * dp],     ph, bl4[0], bl4[2]);
                mma16816(oacc[2 * dp],     pl, bh4[0], bh4[2]);
                mma16816(oacc[2 * dp + 1], ph, bh4[1], bh4[3]);
                mma16816(oacc[2 * dp + 1], ph, bl4[1], bl4[3]);
                mma16816(oacc[2 * dp + 1], pl, bh4[1], bh4[3]);
            }
        }

        if (lane == 0) mbar_arrive(mb + 16 + 8 * s);  // empty[s]
        if (s == 1) pf ^= 1;
    }

    // ---- normalize + store ----
    rs0 += __shfl_xor_sync(0xffffffffu, rs0, 1);
    rs0 += __shfl_xor_sync(0xffffffffu, rs0, 2);
    rs1 += __shfl_xor_sync(0xffffffffu, rs1, 1);
    rs1 += __shfl_xor_sync(0xffffffffu, rs1, 2);
    const float inv0 = 1.0f / rs0;
    const float inv1 = 1.0f / rs1;

    float* og0 = out + ((long)bh * SEQ + (long)qt * BM + row0) * HD;
    float* og1 = og0 + 8 * HD;
#pragma unroll
    for (int dt = 0; dt < 16; ++dt) {
        int c = dt * 8 + qq * 2;
        float2 a, b;
        a.x = oacc[dt][0] * inv0; a.y = oacc[dt][1] * inv0;
        b.x = oacc[dt][2] * inv1; b.y = oacc[dt][3] * inv1;
        *(float2*)(og0 + c) = a;
        *(float2*)(og1 + c) = b;
    }
}

extern "C" void kernel_launch(void* const* d_in, const int* in_sizes, int n_in,
                              void* d_out, int out_size) {
    const float* q = (const float*)d_in[0];
    const float* k = (const float*)d_in[1];
    const float* v = (const float*)d_in[2];
    const float* alpha = (const float*)d_in[3];
    float* out = (float*)d_out;

    int bh = in_sizes[0] / (SEQ * HD);  // B*H = 32

    cudaFuncSetAttribute(adaptive_attn_ws,
                         cudaFuncAttributeMaxDynamicSharedMemorySize, SMEM_BYTES);

    dim3 grid(SEQ / BM, bh);
    adaptive_attn_ws<<<grid, NTH, SMEM_BYTES>>>(q, k, v, alpha, out);
}

// round 10
// speedup vs baseline: 1.9027x; 1.3863x over previous
#include <cuda_runtime.h>
#include <cuda_bf16.h>
#include <cuda_fp16.h>
#include <cstdint>

#define SEQ 2048
#define HD  128
#define BM  128
#define BN  64
#define NTH 384          // 8 consumer warps + 4 producer warps
#define NCONS 256
#define ITERS (SEQ / BN)

// ring: 2 stages x (KHI,KLO bf16 + VH fp16) 16KB each = 48KB/stage
#define TILE_B  16384
#define STAGE_B (3 * TILE_B)
#define SM_QHI  (2 * STAGE_B)          // 98304
#define SM_QLO  (SM_QHI + 32768)       // 131072
#define SMEM_BYTES (SM_QLO + 32768)    // 163840

#define MAX_SLACK 6.0f   // rescale only when tile max exceeds m_used + slack; p <= e^6

// swizzled byte offset of (row, d) in a tile with 256B rows (16-bit, 128 cols)
__device__ __forceinline__ uint32_t swz(int row, int d) {
    return ((uint32_t)row << 8) + ((((uint32_t)(d >> 3)) ^ (row & 7)) << 4) + (d & 7) * 2;
}

__device__ __forceinline__ uint32_t prmt_hi(float a, float b) {
    uint32_t r;
    asm("prmt.b32 %0, %1, %2, 0x7632;" : "=r"(r)
        : "r"(__float_as_uint(a)), "r"(__float_as_uint(b)));
    return r;
}
__device__ __forceinline__ uint32_t pack_lo(float a, float b) {
    float la = a - __uint_as_float(__float_as_uint(a) & 0xffff0000u);
    float lb = b - __uint_as_float(__float_as_uint(b) & 0xffff0000u);
    uint32_t r;
    asm("cvt.rn.bf16x2.f32 %0, %1, %2;" : "=r"(r) : "f"(lb), "f"(la));  // low = la
    return r;
}
__device__ __forceinline__ uint32_t pack_h2(float a, float b) {
    __half2 h = __floats2half2_rn(a, b);   // low = a
    return *(uint32_t*)&h;
}

__device__ __forceinline__ void mma16816(float* c, const uint32_t* a, uint32_t b0, uint32_t b1) {
    asm volatile(
        "mma.sync.aligned.m16n8k16.row.col.f32.bf16.bf16.f32 "
        "{%0,%1,%2,%3}, {%4,%5,%6,%7}, {%8,%9}, {%0,%1,%2,%3};"
        : "+f"(c[0]), "+f"(c[1]), "+f"(c[2]), "+f"(c[3])
        : "r"(a[0]), "r"(a[1]), "r"(a[2]), "r"(a[3]), "r"(b0), "r"(b1));
}
__device__ __forceinline__ void mma16816h(float* c, const uint32_t* a, uint32_t b0, uint32_t b1) {
    asm volatile(
        "mma.sync.aligned.m16n8k16.row.col.f32.f16.f16.f32 "
        "{%0,%1,%2,%3}, {%4,%5,%6,%7}, {%8,%9}, {%0,%1,%2,%3};"
        : "+f"(c[0]), "+f"(c[1]), "+f"(c[2]), "+f"(c[3])
        : "r"(a[0]), "r"(a[1]), "r"(a[2]), "r"(a[3]), "r"(b0), "r"(b1));
}
__device__ __forceinline__ void ldmx4(uint32_t* r, uint32_t addr) {
    asm volatile("ldmatrix.sync.aligned.m8n8.x4.shared.b16 {%0,%1,%2,%3}, [%4];"
                 : "=r"(r[0]), "=r"(r[1]), "=r"(r[2]), "=r"(r[3]) : "r"(addr));
}
__device__ __forceinline__ void ldmx4t(uint32_t* r, uint32_t addr) {
    asm volatile("ldmatrix.sync.aligned.m8n8.x4.trans.shared.b16 {%0,%1,%2,%3}, [%4];"
                 : "=r"(r[0]), "=r"(r[1]), "=r"(r[2]), "=r"(r[3]) : "r"(addr));
}
__device__ __forceinline__ void sts2(uint32_t addr, uint32_t x, uint32_t y) {
    asm volatile("st.shared.v2.b32 [%0], {%1, %2};" :: "r"(addr), "r"(x), "r"(y) : "memory");
}
__device__ __forceinline__ uint32_t smem_u32(const void* p) {
    uint32_t a;
    asm("{ .reg .u64 t; cvta.to.shared.u64 t, %1; cvt.u32.u64 %0, t; }" : "=r"(a) : "l"(p));
    return a;
}
__device__ __forceinline__ void mbar_init(uint32_t m, uint32_t cnt) {
    asm volatile("mbarrier.init.shared.b64 [%0], %1;" :: "r"(m), "r"(cnt) : "memory");
}
__device__ __forceinline__ void mbar_arrive(uint32_t m) {
    asm volatile("mbarrier.arrive.shared.b64 _, [%0];" :: "r"(m) : "memory");
}
__device__ __forceinline__ void mbar_wait(uint32_t m, uint32_t parity) {
    uint32_t done;
    asm volatile("{\n\t.reg .pred p;\n\t"
                 "mbarrier.try_wait.parity.acquire.cta.shared::cta.b64 p, [%1], %2;\n\t"
                 "selp.b32 %0, 1, 0, p;\n\t}"
                 : "=r"(done) : "r"(m), "r"(parity) : "memory");
    while (!done) {
        asm volatile("{\n\t.reg .pred p;\n\t"
                     "mbarrier.try_wait.parity.acquire.cta.shared::cta.b64 p, [%1], %2, 0x989680;\n\t"
                     "selp.b32 %0, 1, 0, p;\n\t}"
                     : "=r"(done) : "r"(m), "r"(parity) : "memory");
    }
}

__global__ void __launch_bounds__(NTH, 1)
adaptive_attn_ws(const float* __restrict__ q,
                 const float* __restrict__ k,
                 const float* __restrict__ v,
                 const float* __restrict__ alpha_p,
                 float* __restrict__ out) {
    extern __shared__ char smem[];
    __shared__ alignas(8) unsigned long long mbars[4];  // full0, full1, empty0, empty1
    const uint32_t sb = smem_u32(smem);
    const uint32_t mb = smem_u32(mbars);

    const int tid = threadIdx.x;
    const int qt = blockIdx.x;
    const int bh = blockIdx.y;
    const float av = alpha_p[0];

    const float* qg = q + ((long)bh * SEQ + (long)qt * BM) * HD;
    const float* kg = k + (long)bh * SEQ * HD;
    const float* vg = v + (long)bh * SEQ * HD;

    if (tid == 0) {
        mbar_init(mb + 0, 128);  // full[0]  : 128 producer threads
        mbar_init(mb + 8, 128);  // full[1]
        mbar_init(mb + 16, 8);   // empty[0] : 8 consumer warps (lane 0)
        mbar_init(mb + 24, 8);   // empty[1]
    }

    // ---- prologue: Q (alpha folded) -> bf16 hi/lo swizzled smem, all threads ----
    for (int idx = tid; idx < BM * HD / 4; idx += NTH) {
        int r = idx >> 5;
        int d = (idx & 31) << 2;
        float4 x = *(const float4*)(qg + r * HD + d);
        x.x *= av; x.y *= av; x.z *= av; x.w *= av;
        uint32_t off = swz(r, d);
        sts2(sb + SM_QHI + off, prmt_hi(x.x, x.y), prmt_hi(x.z, x.w));
        sts2(sb + SM_QLO + off, pack_lo(x.x, x.y), pack_lo(x.z, x.w));
    }
    __syncthreads();

    if (tid >= NCONS) {
        // ================= PRODUCER (warps 8-11) =================
        const int pt = tid - NCONS;  // 0..127
        uint32_t pe = 1;             // empty-wait phase (first pass free)
        for (int i = 0; i < ITERS; ++i) {
            const int s = i & 1;
            mbar_wait(mb + 16 + 8 * s, pe);
            const uint32_t base = sb + (uint32_t)s * STAGE_B;
            const float* kp = kg + (long)i * BN * HD;
            const float* vp = vg + (long)i * BN * HD;
            float4 xb[8];
#pragma unroll
            for (int h = 0; h < 2; ++h) {
#pragma unroll
                for (int t = 0; t < 8; ++t) {
                    int idx = pt + (h * 8 + t) * 128;
                    xb[t] = *(const float4*)(kp + (idx >> 5) * HD + ((idx & 31) << 2));
                }
#pragma unroll
                for (int t = 0; t < 8; ++t) {
                    int idx = pt + (h * 8 + t) * 128;
                    uint32_t off = swz(idx >> 5, (idx & 31) << 2);
                    sts2(base + off, prmt_hi(xb[t].x, xb[t].y), prmt_hi(xb[t].z, xb[t].w));
                    sts2(base + TILE_B + off, pack_lo(xb[t].x, xb[t].y), pack_lo(xb[t].z, xb[t].w));
                }
            }
            // V: single fp16 tile
#pragma unroll
            for (int h = 0; h < 2; ++h) {
#pragma unroll
                for (int t = 0; t < 8; ++t) {
                    int idx = pt + (h * 8 + t) * 128;
                    xb[t] = *(const float4*)(vp + (idx >> 5) * HD + ((idx & 31) << 2));
                }
#pragma unroll
                for (int t = 0; t < 8; ++t) {
                    int idx = pt + (h * 8 + t) * 128;
                    uint32_t off = swz(idx >> 5, (idx & 31) << 2);
                    sts2(base + 2 * TILE_B + off, pack_h2(xb[t].x, xb[t].y), pack_h2(xb[t].z, xb[t].w));
                }
            }
            mbar_arrive(mb + 8 * s);  // full[s]
            if (s == 1) pe ^= 1;
        }
        return;
    }

    // ================= CONSUMER (warps 0-7) =================
    const int w = tid >> 5;
    const int lane = tid & 31;
    const int qq = lane & 3;
    const int jj = lane & 7;
    const int g = lane >> 3;
    const int rowadd = jj + ((g >> 1) << 3);        // B-operand ldmatrix row offset
    const int csel = g & 1;                         // B-operand chunk offset
    const int arow = w * 16 + ((g & 1) << 3) + jj;  // A-operand ldmatrix row
    const int asel = g >> 1;                        // A-operand 8-col block
    const int row0 = w * 16 + (lane >> 2);

    float oacc[16][4];
#pragma unroll
    for (int i = 0; i < 16; ++i)
#pragma unroll
        for (int e = 0; e < 4; ++e) oacc[i][e] = 0.0f;
    float rs0 = 0.0f, rs1 = 0.0f;
    float m0 = -1e30f, m1 = -1e30f;   // lazily-updated row max (slack-tolerant)
    uint32_t pf = 0;  // full-wait phase

    const uint32_t qhi_b = sb + SM_QHI;
    const uint32_t qlo_b = sb + SM_QLO;

    for (int i = 0; i < ITERS; ++i) {
        const int s = i & 1;
        mbar_wait(mb + 8 * s, pf);
        const uint32_t base = sb + (uint32_t)s * STAGE_B;
        const uint32_t khi = base, klo = base + TILE_B;
        const uint32_t vh = base + 2 * TILE_B;

        // ---- S = (alpha Q) K^T, bf16x3 ----
        float sf[8][4];
#pragma unroll
        for (int nt = 0; nt < 8; ++nt)
#pragma unroll
            for (int e = 0; e < 4; ++e) sf[nt][e] = 0.0f;

#pragma unroll
        for (int kk = 0; kk < 8; ++kk) {
            uint32_t qa_h[4], qa_l[4];
            uint32_t aoff = ((uint32_t)arow << 8) + ((((kk << 1) | asel) ^ jj) << 4);
            ldmx4(qa_h, qhi_b + aoff);
            ldmx4(qa_l, qlo_b + aoff);
#pragma unroll
            for (int np = 0; np < 4; ++np) {
                uint32_t off = ((uint32_t)(np * 16 + rowadd) << 8)
                             + ((((kk << 1) | csel) ^ jj) << 4);
                uint32_t bh4[4], bl4[4];
                ldmx4(bh4, khi + off);
                ldmx4(bl4, klo + off);
                mma16816(sf[2 * np],     qa_h, bh4[0], bh4[1]);
                mma16816(sf[2 * np],     qa_h, bl4[0], bl4[1]);
                mma16816(sf[2 * np],     qa_l, bh4[0], bh4[1]);
                mma16816(sf[2 * np + 1], qa_h, bh4[2], bh4[3]);
                mma16816(sf[2 * np + 1], qa_h, bl4[2], bl4[3]);
                mma16816(sf[2 * np + 1], qa_l, bh4[2], bh4[3]);
            }
        }

        // ---- lazy max: rescale only when tile max exceeds m_used + slack ----
        float tm0 = sf[0][0], tm1 = sf[0][2];
#pragma unroll
        for (int nt = 0; nt < 8; ++nt) {
            tm0 = fmaxf(tm0, fmaxf(sf[nt][0], sf[nt][1]));
            tm1 = fmaxf(tm1, fmaxf(sf[nt][2], sf[nt][3]));
        }
        tm0 = fmaxf(tm0, __shfl_xor_sync(0xffffffffu, tm0, 1));
        tm0 = fmaxf(tm0, __shfl_xor_sync(0xffffffffu, tm0, 2));
        tm1 = fmaxf(tm1, __shfl_xor_sync(0xffffffffu, tm1, 1));
        tm1 = fmaxf(tm1, __shfl_xor_sync(0xffffffffu, tm1, 2));
        const bool trig = (tm0 > m0 + MAX_SLACK) || (tm1 > m1 + MAX_SLACK);
        if (__ballot_sync(0xffffffffu, trig)) {
            const float m0n = fmaxf(m0, tm0);
            const float m1n = fmaxf(m1, tm1);
            const float sc0 = __expf(m0 - m0n);
            const float sc1 = __expf(m1 - m1n);
            rs0 *= sc0; rs1 *= sc1;
#pragma unroll
            for (int dt = 0; dt < 16; ++dt) {
                oacc[dt][0] *= sc0; oacc[dt][1] *= sc0;
                oacc[dt][2] *= sc1; oacc[dt][3] *= sc1;
            }
            m0 = m0n; m1 = m1n;
        }

        // ---- per 16-col chunk: p = exp(l - m) in fp16, then its PV mmas ----
#pragma unroll
        for (int kk = 0; kk < 4; ++kk) {
            float p00 = __expf(sf[2 * kk][0] - m0);
            float p01 = __expf(sf[2 * kk][1] - m0);
            float p02 = __expf(sf[2 * kk][2] - m1);
            float p03 = __expf(sf[2 * kk][3] - m1);
            float p10 = __expf(sf[2 * kk + 1][0] - m0);
            float p11 = __expf(sf[2 * kk + 1][1] - m0);
            float p12 = __expf(sf[2 * kk + 1][2] - m1);
            float p13 = __expf(sf[2 * kk + 1][3] - m1);
            rs0 += p00 + p01 + p10 + p11;
            rs1 += p02 + p03 + p12 + p13;

            uint32_t ph[4];
            ph[0] = pack_h2(p00, p01);
            ph[1] = pack_h2(p02, p03);
            ph[2] = pack_h2(p10, p11);
            ph[3] = pack_h2(p12, p13);

#pragma unroll
            for (int dp = 0; dp < 8; ++dp) {
                uint32_t off = ((uint32_t)(kk * 16 + rowadd) << 8)
                             + ((((dp << 1) | csel) ^ jj) << 4);
                uint32_t bv[4];
                ldmx4t(bv, vh + off);
                mma16816h(oacc[2 * dp],     ph, bv[0], bv[2]);
                mma16816h(oacc[2 * dp + 1], ph, bv[1], bv[3]);
            }
        }

        if (lane == 0) mbar_arrive(mb + 16 + 8 * s);  // empty[s]
        if (s == 1) pf ^= 1;
    }

    // ---- normalize + store (lazy-max shift cancels in O/l) ----
    rs0 += __shfl_xor_sync(0xffffffffu, rs0, 1);
    rs0 += __shfl_xor_sync(0xffffffffu, rs0, 2);
    rs1 += __shfl_xor_sync(0xffffffffu, rs1, 1);
    rs1 += __shfl_xor_sync(0xffffffffu, rs1, 2);
    const float inv0 = 1.0f / rs0;
    const float inv1 = 1.0f / rs1;

    float* og0 = out + ((long)bh * SEQ + (long)qt * BM + row0) * HD;
    float* og1 = og0 + 8 * HD;
#pragma unroll
    for (int dt = 0; dt < 16; ++dt) {
        int c = dt * 8 + qq * 2;
        float2 a, b;
        a.x = oacc[dt][0] * inv0; a.y = oacc[dt][1] * inv0;
        b.x = oacc[dt][2] * inv1; b.y = oacc[dt][3] * inv1;
        *(float2*)(og0 + c) = a;
        *(float2*)(og1 + c) = b;
    }
}

extern "C" void kernel_launch(void* const* d_in, const int* in_sizes, int n_in,
                              void* d_out, int out_size) {
    const float* q = (const float*)d_in[0];
    const float* k = (const float*)d_in[1];
    const float* v = (const float*)d_in[2];
    const float* alpha = (const float*)d_in[3];
    float* out = (float*)d_out;

    int bh = in_sizes[0] / (SEQ * HD);  // B*H = 32

    cudaFuncSetAttribute(adaptive_attn_ws,
                         cudaFuncAttributeMaxDynamicSharedMemorySize, SMEM_BYTES);

    dim3 grid(SEQ / BM, bh);
    adaptive_attn_ws<<<grid, NTH, SMEM_BYTES>>>(q, k, v, alpha, out);
}